// round 15
// baseline (speedup 1.0000x reference)
#include <cuda_runtime.h>
#include <cuda_fp16.h>
#include <cstdint>

#define N_UE 100000
#define N_AP 10000
#define N_E  1600000
#define DD   64
#define HH   128
#define SCAT_BLOCKS ((N_E + 255) / 256)     // 6250
#define UEP_BLOCKS  ((N_UE + 63) / 64)      // 1563
#define MAIN_BLOCKS (N_E / 256)             // 6250 (2 tiles of 128 per block)

// ---------------- scratch (device globals; no allocation allowed) ----------
// Invariant: g_cnt == 0 and g_agg == 0 at every kernel_launch entry.
__device__ __half g_ueproj[(size_t)N_UE * HH];   // ue_hid @ W1a[64:] + b1a (fp16)
__device__ float  g_agg[(size_t)N_AP * HH];      // segment_sum(relu(...))
__device__ int    g_cnt[N_AP];
__device__ int    g_cursor[N_AP];
__device__ int4   g_meta[N_E];                   // (edge_idx, src, dst, 0) sorted by dst
__device__ unsigned g_wt[4096];                  // W1a[:64]^T as half2 pairs [n][k2]

__device__ __forceinline__ uint32_t smem_u32(const void* p) {
    uint32_t a;
    asm("{ .reg .u64 t; cvta.to.shared.u64 t, %1; cvt.u32.u64 %0, t; }" : "=r"(a) : "l"(p));
    return a;
}

// ---------------- launch 0: histogram --------------------------------------
__global__ void k_hist(const int* __restrict__ dst) {
    int i = blockIdx.x * 256 + threadIdx.x;
    if (i < N_E) atomicAdd(&g_cnt[dst[i]], 1);
}

// ---------------- launch 1: scan + weight prep ------------------------------
__global__ void k_scan_prep(const float* __restrict__ W1a) {
    if (blockIdx.x == 0) {
        __shared__ int buf[1024];
        int t = threadIdx.x;
        int local[16];
        int s = 0;
        if (t < 625) {
            #pragma unroll
            for (int j = 0; j < 16; j++) { local[j] = s; s += g_cnt[t * 16 + j]; }
        }
        buf[t] = s;
        __syncthreads();
        int own = s;
        for (int off = 1; off < 1024; off <<= 1) {
            int v = 0;
            if (t >= off) v = buf[t - off];
            __syncthreads();
            buf[t] += v;
            __syncthreads();
        }
        int excl = buf[t] - own;
        if (t < 625) {
            #pragma unroll
            for (int j = 0; j < 16; j++) g_cursor[t * 16 + j] = excl + local[j];
        }
    } else {
        int j = (blockIdx.x - 1) * 1024 + threadIdx.x;   // 4096 half2 pairs
        if (j < 4096) {
            int n = j >> 5, k2 = j & 31;                 // pair covers k = 2*k2, 2*k2+1
            float v0 = W1a[(k2 * 2) * HH + n];           // Wt[n][k] = W1a[k][n], k<64
            float v1 = W1a[(k2 * 2 + 1) * HH + n];
            __half2 h = __floats2half2_rn(v0, v1);
            g_wt[j] = *(unsigned*)&h;
        }
    }
}

// ---------------- launch 2: fused scatter + ue projection -------------------
__global__ void __launch_bounds__(256) k_scatter_ueproj(
    const int* __restrict__ src, const int* __restrict__ dst,
    const float* __restrict__ ue_hid, const float* __restrict__ W1a,
    const float* __restrict__ b1a)
{
    __shared__ float us[64][64];
    int t = threadIdx.x;

    if (blockIdx.x < SCAT_BLOCKS) {
        int i = blockIdx.x * 256 + t;
        if (i < N_E) {
            int d = dst[i];
            int p = atomicAdd(&g_cursor[d], 1);
            g_meta[p] = make_int4(i, src[i], d, 0);
        }
        return;
    }

    int rbase = (blockIdx.x - SCAT_BLOCKS) * 64;

    for (int f = t; f < 1024; f += 256) {
        int row = f >> 4, c4 = f & 15;
        float4 v = make_float4(0.f, 0.f, 0.f, 0.f);
        if (rbase + row < N_UE)
            v = *(const float4*)(ue_hid + (size_t)(rbase + row) * DD + c4 * 4);
        *(float4*)(&us[row][c4 * 4]) = v;
    }

    int c = t & 127;
    int rh = t >> 7;
    float wc[64];
    #pragma unroll 8
    for (int k = 0; k < 64; k++) wc[k] = W1a[(64 + k) * HH + c];
    float bb = b1a[c];
    __syncthreads();

    for (int i = 0; i < 32; i++) {
        int r = rh * 32 + i;
        int gr = rbase + r;
        if (gr >= N_UE) break;          // uniform per warp
        float acc = bb;
        #pragma unroll
        for (int k4 = 0; k4 < 16; k4++) {
            float4 u4 = *(const float4*)(&us[r][k4 * 4]);
            acc += u4.x * wc[k4 * 4 + 0];
            acc += u4.y * wc[k4 * 4 + 1];
            acc += u4.z * wc[k4 * 4 + 2];
            acc += u4.w * wc[k4 * 4 + 3];
        }
        g_ueproj[(size_t)gr * HH + c] = __float2half(acc);
    }
}

// ---------------- launch 3: main edge kernel (PROFILED INDEX) ---------------
__device__ __forceinline__ void mma_f16(float c[4],
    unsigned a0, unsigned a1, unsigned a2, unsigned a3,
    unsigned b0, unsigned b1)
{
    asm volatile(
        "mma.sync.aligned.m16n8k16.row.col.f32.f16.f16.f32 "
        "{%0,%1,%2,%3}, {%4,%5,%6,%7}, {%8,%9}, {%0,%1,%2,%3};\n"
        : "+f"(c[0]), "+f"(c[1]), "+f"(c[2]), "+f"(c[3])
        : "r"(a0), "r"(a1), "r"(a2), "r"(a3), "r"(b0), "r"(b1));
}

#define LDM4(r0, r1, r2, r3, addr)                                              \
    asm volatile("ldmatrix.sync.aligned.m8n8.x4.shared.b16 {%0,%1,%2,%3}, [%4];" \
                 : "=r"(r0), "=r"(r1), "=r"(r2), "=r"(r3) : "r"(addr))

#define ASTR 72                          // padded smem stride (f16 elems)
#define HSTRH 136                        // Hs stride in halves (conflict-free)
// layout: Ah[128][72] | B[128][72] | Hs[128][136]
#define SMEM_A  0
#define SMEM_B  (128 * ASTR * 2)                 // 18432
#define SMEM_HS (2 * 128 * ASTR * 2)             // 36864
#define SMEM_MAIN (SMEM_HS + 128 * HSTRH * 2)    // 71680 B

__global__ void __launch_bounds__(256, 2) k_main(const float* __restrict__ edge_hid)
{
    extern __shared__ char sraw[];
    __half* Ah = (__half*)(sraw + SMEM_A);
    __half* Bs = (__half*)(sraw + SMEM_B);
    __half2* Hs2 = (__half2*)(sraw + SMEM_HS);
    __shared__ int s_eid[128];
    __shared__ int s_src[128];
    __shared__ int s_dst[128];

    int t = threadIdx.x;
    int w = t >> 5, l = t & 31;
    int wr = w & 3, wc = w >> 2;         // warp tile: rows [32wr,+32) x cols [64wc,+64)
    int g = l >> 2, q4 = l & 3;
    int lm = l >> 3, lr = l & 7;

    // stage weights ONCE per block (single f16 plane, uint4-vectorized)
    {
        const uint4* wsrc = (const uint4*)g_wt;
        for (int j = t; j < 1024; j += 256) {
            int n = j >> 3, q = j & 7;   // 8 uint4 (=64 halves) per n-row
            ((uint4*)(Bs + n * ASTR))[q] = wsrc[n * 8 + q];
        }
    }

    // ldmatrix lane addresses
    uint32_t aA0 = smem_u32(Ah) + (uint32_t)(((32 * wr + (lm & 1) * 8 + lr) * ASTR
                                              + (lm >> 1) * 8) * 2);
    uint32_t aA1 = aA0 + 16 * ASTR * 2;
    uint32_t bOff = (uint32_t)((((lm >> 1) * 8 + lr) * ASTR + (lm & 1) * 8) * 2);
    uint32_t aB = smem_u32(Bs) + (uint32_t)(64 * wc * ASTR * 2) + bOff;

    #pragma unroll 1
    for (int it = 0; it < 2; it++) {
        int base = blockIdx.x * 256 + it * 128;

        __syncthreads();   // weights staged (it0) / prev reduce done (it1)

        // meta -> smem
        if (t < 128) {
            int4 m = g_meta[base + t];
            s_eid[t] = m.x;
            s_src[t] = m.y;
            s_dst[t] = m.z;
        }
        __syncthreads();

        // COALESCED gather + convert: pass q covers rows q*16+(t>>4), chunk = t&15.
        // Warp reads 2 rows x 256B contiguous -> 4 wavefronts/instr (was 32).
        {
            int rloc = t >> 4, chunk = t & 15;
            #pragma unroll
            for (int q = 0; q < 8; q++) {
                int row = q * 16 + rloc;
                int e = s_eid[row];
                float4 v = *(const float4*)(edge_hid + (size_t)e * DD + chunk * 4);
                __half2 h01 = __floats2half2_rn(v.x, v.y);
                __half2 h23 = __floats2half2_rn(v.z, v.w);
                uint2 pk = make_uint2(*(unsigned*)&h01, *(unsigned*)&h23);
                *(uint2*)(Ah + row * ASTR + chunk * 4) = pk;   // STS.64
            }
        }
        __syncthreads();

        float C[2][8][4];
        #pragma unroll
        for (int mt = 0; mt < 2; mt++)
            #pragma unroll
            for (int nf = 0; nf < 8; nf++)
                { C[mt][nf][0] = C[mt][nf][1] = C[mt][nf][2] = C[mt][nf][3] = 0.f; }

        #pragma unroll
        for (int kt = 0; kt < 4; kt++) {
            unsigned a0, a1, a2, a3, a4, a5, a6, a7;
            LDM4(a0, a1, a2, a3, aA0 + kt * 32);
            LDM4(a4, a5, a6, a7, aA1 + kt * 32);
            #pragma unroll
            for (int pp = 0; pp < 4; pp++) {          // n-tiles 2pp, 2pp+1
                unsigned b0, b1, b2, b3;
                LDM4(b0, b1, b2, b3, aB + (uint32_t)(16 * pp * ASTR * 2) + kt * 32);
                mma_f16(C[0][2 * pp],     a0, a1, a2, a3, b0, b1);
                mma_f16(C[0][2 * pp + 1], a0, a1, a2, a3, b2, b3);
                mma_f16(C[1][2 * pp],     a4, a5, a6, a7, b0, b1);
                mma_f16(C[1][2 * pp + 1], a4, a5, a6, a7, b2, b3);
            }
        }

        // epilogue: store raw C as f16 to Hs (no global traffic here)
        {
            int r0 = 32 * wr + g;
            #pragma unroll
            for (int mt = 0; mt < 2; mt++) {
                #pragma unroll
                for (int nf = 0; nf < 8; nf++) {
                    int c0 = 64 * wc + 8 * nf + q4 * 2;
                    __half2 v0 = __floats2half2_rn(C[mt][nf][0], C[mt][nf][1]);
                    __half2 v1 = __floats2half2_rn(C[mt][nf][2], C[mt][nf][3]);
                    int rA = r0 + mt * 16;
                    Hs2[rA * (HSTRH / 2) + (c0 >> 1)] = v0;
                    Hs2[(rA + 8) * (HSTRH / 2) + (c0 >> 1)] = v1;
                }
            }
        }
        __syncthreads();

        // segmented reduce over sorted dst: 8 strips of 16 rows.
        // ueproj add + relu fused here: warp-coalesced 256B row loads (2 wf/instr),
        // all 16 preloaded upfront (independent, MLP=16; C regs are dead).
        {
            int c4 = t & 31, qr = t >> 5;     // lane covers float cols [4c4, 4c4+4)
            int r0 = qr * 16;
            uint2 upk[16];
            #pragma unroll
            for (int i = 0; i < 16; i++)
                upk[i] = *(const uint2*)(g_ueproj + (size_t)s_src[r0 + i] * HH + c4 * 4);

            float acc0 = 0.f, acc1 = 0.f, acc2 = 0.f, acc3 = 0.f;
            int prev = s_dst[r0];
            float* aggp = g_agg + (size_t)prev * HH + c4 * 4;
            #pragma unroll
            for (int i = 0; i < 16; i++) {
                int r = r0 + i;
                int d = s_dst[r];
                if (d != prev) {
                    atomicAdd(aggp + 0, acc0);
                    atomicAdd(aggp + 1, acc1);
                    atomicAdd(aggp + 2, acc2);
                    atomicAdd(aggp + 3, acc3);
                    acc0 = acc1 = acc2 = acc3 = 0.f;
                    prev = d;
                    aggp = g_agg + (size_t)prev * HH + c4 * 4;
                }
                uint2 pk = *(const uint2*)(Hs2 + r * (HSTRH / 2) + c4 * 2);  // LDS.64
                float2 hv0 = __half22float2(*(__half2*)&pk.x);
                float2 hv1 = __half22float2(*(__half2*)&pk.y);
                float2 u0 = __half22float2(*(__half2*)&upk[i].x);
                float2 u1 = __half22float2(*(__half2*)&upk[i].y);
                acc0 += fmaxf(hv0.x + u0.x, 0.f);
                acc1 += fmaxf(hv0.y + u0.y, 0.f);
                acc2 += fmaxf(hv1.x + u1.x, 0.f);
                acc3 += fmaxf(hv1.y + u1.y, 0.f);
            }
            atomicAdd(aggp + 0, acc0);
            atomicAdd(aggp + 1, acc1);
            atomicAdd(aggp + 2, acc2);
            atomicAdd(aggp + 3, acc3);
        }
    }
}

// ---------------- launch 4: final AP MLP + scratch cleanup ------------------
__global__ void __launch_bounds__(128) k_final(
    const float* __restrict__ ap_hid,
    const float* __restrict__ W1b, const float* __restrict__ b1b,
    const float* __restrict__ W2a, const float* __restrict__ b2a,
    const float* __restrict__ W2b, const float* __restrict__ b2b,
    float* __restrict__ out)
{
    __shared__ float Ss[16][128];
    __shared__ float Zs[16][192];
    __shared__ float Ys[16][128];
    __shared__ float sdeg[16];

    int t = threadIdx.x;
    int a0 = blockIdx.x * 16;

    for (int i = t; i < 16 * 128; i += 128)
        Ss[i >> 7][i & 127] = g_agg[(size_t)a0 * HH + i];
    if (t < 16) sdeg[t] = (float)g_cnt[a0 + t];
    for (int i = t; i < 16 * 64; i += 128)
        Zs[i >> 6][i & 63] = ap_hid[(size_t)a0 * DD + i];
    __syncthreads();

    // restore scratch invariant for the next kernel_launch call
    for (int i = t; i < 16 * 128; i += 128)
        g_agg[(size_t)a0 * HH + i] = 0.f;
    if (t < 16) g_cnt[a0 + t] = 0;

    // stage 1: Zs[r][64+c] = deg[r]*b1b[c] + sum_k Ss[r][k]*W1b[k][c]
    {
        int c = t;
        float acc[16];
        float bb = b1b[c];
        #pragma unroll
        for (int r = 0; r < 16; r++) acc[r] = sdeg[r] * bb;
        for (int k = 0; k < 128; k++) {
            float wv = W1b[k * HH + c];
            #pragma unroll
            for (int r = 0; r < 16; r++) acc[r] += Ss[r][k] * wv;
        }
        #pragma unroll
        for (int r = 0; r < 16; r++) Zs[r][64 + c] = acc[r];
    }
    __syncthreads();

    // stage 2: Ys = relu(Zs @ W2a + b2a)
    {
        int c = t;
        float acc[16];
        float bb = b2a[c];
        #pragma unroll
        for (int r = 0; r < 16; r++) acc[r] = bb;
        for (int k = 0; k < 192; k++) {
            float wv = W2a[k * HH + c];
            #pragma unroll
            for (int r = 0; r < 16; r++) acc[r] += Zs[r][k] * wv;
        }
        #pragma unroll
        for (int r = 0; r < 16; r++) Ys[r][c] = fmaxf(acc[r], 0.f);
    }
    __syncthreads();

    // stage 3: out = Ys @ W2b + b2b
    {
        int c = t & 63, rg = t >> 6;
        float acc[8];
        float bb = b2b[c];
        #pragma unroll
        for (int j = 0; j < 8; j++) acc[j] = bb;
        for (int k = 0; k < 128; k++) {
            float wv = W2b[k * DD + c];
            #pragma unroll
            for (int j = 0; j < 8; j++) acc[j] += Ys[rg * 8 + j][k] * wv;
        }
        #pragma unroll
        for (int j = 0; j < 8; j++)
            out[(size_t)(a0 + rg * 8 + j) * DD + c] = acc[j];
    }
}

// ---------------- launch ----------------------------------------------------
extern "C" void kernel_launch(void* const* d_in, const int* in_sizes, int n_in,
                              void* d_out, int out_size) {
    const float* ue_hid   = (const float*)d_in[0];
    const float* ap_hid   = (const float*)d_in[1];
    const float* edge_hid = (const float*)d_in[2];
    const int*   src      = (const int*)d_in[3];
    const int*   dst      = (const int*)d_in[4];
    const float* W1a      = (const float*)d_in[5];
    const float* b1a      = (const float*)d_in[6];
    const float* W1b      = (const float*)d_in[7];
    const float* b1b      = (const float*)d_in[8];
    const float* W2a      = (const float*)d_in[9];
    const float* b2a      = (const float*)d_in[10];
    const float* W2b      = (const float*)d_in[11];
    const float* b2b      = (const float*)d_in[12];
    float* out = (float*)d_out;

    cudaFuncSetAttribute(k_main, cudaFuncAttributeMaxDynamicSharedMemorySize, SMEM_MAIN);

    k_hist<<<SCAT_BLOCKS, 256>>>(dst);                                     // 0
    k_scan_prep<<<5, 1024>>>(W1a);                                         // 1
    k_scatter_ueproj<<<SCAT_BLOCKS + UEP_BLOCKS, 256>>>(src, dst,
                                                        ue_hid, W1a, b1a); // 2
    k_main<<<MAIN_BLOCKS, 256, SMEM_MAIN>>>(edge_hid);                     // 3 (profiled)
    k_final<<<N_AP / 16, 128>>>(ap_hid, W1b, b1b, W2a, b2a, W2b, b2b, out);// 4
}

// round 17
// speedup vs baseline: 1.5409x; 1.5409x over previous
#include <cuda_runtime.h>
#include <cuda_fp16.h>
#include <cstdint>

#define N_UE 100000
#define N_AP 10000
#define N_E  1600000
#define DD   64
#define HH   128
#define SCAT_BLOCKS ((N_E + 255) / 256)     // 6250
#define UEP_BLOCKS  ((N_UE + 63) / 64)      // 1563
#define NT   4                              // tiles (of 128 edges) per block
#define MAIN_BLOCKS (N_E / (128 * NT))      // 3125

// ---------------- scratch (device globals; no allocation allowed) ----------
// Invariant: g_cnt == 0 and g_agg == 0 at every kernel_launch entry.
__device__ __half g_ueproj[(size_t)N_UE * HH];   // ue_hid @ W1a[64:] + b1a (fp16)
__device__ float  g_agg[(size_t)N_AP * HH];      // segment_sum(relu(...))
__device__ int    g_cnt[N_AP];
__device__ int    g_cursor[N_AP];
__device__ int4   g_meta[N_E];                   // (edge_idx, src, dst, 0) sorted by dst
__device__ unsigned g_wt[4096];                  // W1a[:64]^T as half2 pairs [n][k2]

__device__ __forceinline__ uint32_t smem_u32(const void* p) {
    uint32_t a;
    asm("{ .reg .u64 t; cvta.to.shared.u64 t, %1; cvt.u32.u64 %0, t; }" : "=r"(a) : "l"(p));
    return a;
}

#define CP_ASYNC16(saddr, gptr)                                                \
    asm volatile("cp.async.cg.shared.global [%0], [%1], 16;"                   \
                 :: "r"(saddr), "l"(gptr) : "memory")
#define CP_COMMIT()  asm volatile("cp.async.commit_group;" ::: "memory")
#define CP_WAIT0()   asm volatile("cp.async.wait_group 0;" ::: "memory")

// ---------------- launch 0: histogram --------------------------------------
__global__ void k_hist(const int* __restrict__ dst) {
    int i = blockIdx.x * 256 + threadIdx.x;
    if (i < N_E) atomicAdd(&g_cnt[dst[i]], 1);
}

// ---------------- launch 1: scan + weight prep ------------------------------
__global__ void k_scan_prep(const float* __restrict__ W1a) {
    if (blockIdx.x == 0) {
        __shared__ int buf[1024];
        int t = threadIdx.x;
        int local[16];
        int s = 0;
        if (t < 625) {
            #pragma unroll
            for (int j = 0; j < 16; j++) { local[j] = s; s += g_cnt[t * 16 + j]; }
        }
        buf[t] = s;
        __syncthreads();
        int own = s;
        for (int off = 1; off < 1024; off <<= 1) {
            int v = 0;
            if (t >= off) v = buf[t - off];
            __syncthreads();
            buf[t] += v;
            __syncthreads();
        }
        int excl = buf[t] - own;
        if (t < 625) {
            #pragma unroll
            for (int j = 0; j < 16; j++) g_cursor[t * 16 + j] = excl + local[j];
        }
    } else {
        int j = (blockIdx.x - 1) * 1024 + threadIdx.x;   // 4096 half2 pairs
        if (j < 4096) {
            int n = j >> 5, k2 = j & 31;                 // pair covers k = 2*k2, 2*k2+1
            float v0 = W1a[(k2 * 2) * HH + n];           // Wt[n][k] = W1a[k][n], k<64
            float v1 = W1a[(k2 * 2 + 1) * HH + n];
            __half2 h = __floats2half2_rn(v0, v1);
            g_wt[j] = *(unsigned*)&h;
        }
    }
}

// ---------------- launch 2: fused scatter + ue projection -------------------
__global__ void __launch_bounds__(256) k_scatter_ueproj(
    const int* __restrict__ src, const int* __restrict__ dst,
    const float* __restrict__ ue_hid, const float* __restrict__ W1a,
    const float* __restrict__ b1a)
{
    __shared__ float us[64][64];
    int t = threadIdx.x;

    if (blockIdx.x < SCAT_BLOCKS) {
        int i = blockIdx.x * 256 + t;
        if (i < N_E) {
            int d = dst[i];
            int p = atomicAdd(&g_cursor[d], 1);
            g_meta[p] = make_int4(i, src[i], d, 0);
        }
        return;
    }

    int rbase = (blockIdx.x - SCAT_BLOCKS) * 64;

    for (int f = t; f < 1024; f += 256) {
        int row = f >> 4, c4 = f & 15;
        float4 v = make_float4(0.f, 0.f, 0.f, 0.f);
        if (rbase + row < N_UE)
            v = *(const float4*)(ue_hid + (size_t)(rbase + row) * DD + c4 * 4);
        *(float4*)(&us[row][c4 * 4]) = v;
    }

    int c = t & 127;
    int rh = t >> 7;
    float wc[64];
    #pragma unroll 8
    for (int k = 0; k < 64; k++) wc[k] = W1a[(64 + k) * HH + c];
    float bb = b1a[c];
    __syncthreads();

    for (int i = 0; i < 32; i++) {
        int r = rh * 32 + i;
        int gr = rbase + r;
        if (gr >= N_UE) break;          // uniform per warp
        float acc = bb;
        #pragma unroll
        for (int k4 = 0; k4 < 16; k4++) {
            float4 u4 = *(const float4*)(&us[r][k4 * 4]);
            acc += u4.x * wc[k4 * 4 + 0];
            acc += u4.y * wc[k4 * 4 + 1];
            acc += u4.z * wc[k4 * 4 + 2];
            acc += u4.w * wc[k4 * 4 + 3];
        }
        g_ueproj[(size_t)gr * HH + c] = __float2half(acc);
    }
}

// ---------------- launch 3: main edge kernel (PROFILED INDEX) ---------------
__device__ __forceinline__ void mma_f16(float c[4],
    unsigned a0, unsigned a1, unsigned a2, unsigned a3,
    unsigned b0, unsigned b1)
{
    asm volatile(
        "mma.sync.aligned.m16n8k16.row.col.f32.f16.f16.f32 "
        "{%0,%1,%2,%3}, {%4,%5,%6,%7}, {%8,%9}, {%0,%1,%2,%3};\n"
        : "+f"(c[0]), "+f"(c[1]), "+f"(c[2]), "+f"(c[3])
        : "r"(a0), "r"(a1), "r"(a2), "r"(a3), "r"(b0), "r"(b1));
}

#define LDM4(r0, r1, r2, r3, addr)                                              \
    asm volatile("ldmatrix.sync.aligned.m8n8.x4.shared.b16 {%0,%1,%2,%3}, [%4];" \
                 : "=r"(r0), "=r"(r1), "=r"(r2), "=r"(r3) : "r"(addr))

#define ASTR 72                          // padded f16 smem stride
#define HSTRH 136                        // Hs stride in halves (conflict-free)
// dyn smem: stage f32[128][64] | Ah f16[128][72] | B f16[128][72] | Hs f16[128][136]
#define SMEM_STAGE 0
#define SMEM_A  32768
#define SMEM_B  (SMEM_A + 128 * ASTR * 2)        // 51200
#define SMEM_HS (SMEM_B + 128 * ASTR * 2)        // 69632
#define SMEM_MAIN (SMEM_HS + 128 * HSTRH * 2)    // 104448 B (2 blocks/SM)

__global__ void __launch_bounds__(256, 2) k_main(const float* __restrict__ edge_hid)
{
    extern __shared__ char sraw[];
    float*  Sg  = (float*)(sraw + SMEM_STAGE);
    __half* Ah  = (__half*)(sraw + SMEM_A);
    __half* Bs  = (__half*)(sraw + SMEM_B);
    __half2* Hs2 = (__half2*)(sraw + SMEM_HS);
    __shared__ int s_src[2][128];
    __shared__ int s_dst[2][128];

    int t = threadIdx.x;
    int w = t >> 5, l = t & 31;
    int wr = w & 3, wcg = w >> 2;        // warp tile: rows [32wr,+32) x cols [64wcg,+64)
    int g = l >> 2, q4 = l & 3;
    int lm = l >> 3, lr = l & 7;
    int rloc = t >> 4, chunk = t & 15;   // gather/convert mapping
    int hh = rloc & 1;

    // stage weights ONCE per block
    {
        const uint4* wsrc = (const uint4*)g_wt;
        for (int j = t; j < 1024; j += 256) {
            int n = j >> 3, q = j & 7;
            ((uint4*)(Bs + n * ASTR))[q] = wsrc[n * 8 + q];
        }
    }

    // ldmatrix lane addresses
    uint32_t aA0 = smem_u32(Ah) + (uint32_t)(((32 * wr + (lm & 1) * 8 + lr) * ASTR
                                              + (lm >> 1) * 8) * 2);
    uint32_t aA1 = aA0 + 16 * ASTR * 2;
    uint32_t bOff = (uint32_t)((((lm >> 1) * 8 + lr) * ASTR + (lm & 1) * 8) * 2);
    uint32_t aB = smem_u32(Bs) + (uint32_t)(64 * wcg * ASTR * 2) + bOff;
    uint32_t stageBase = smem_u32(Sg);

    int blk0 = blockIdx.x * (128 * NT);

    // ---- prologue: prefetch meta + issue cp.async gather for tile 0 ----
    {
        int base = blk0;
        int eidl = g_meta[base + (l & 7) * 16 + 2 * w + ((l >> 3) & 1)].x;
        if (t < 128) {
            int4 m = g_meta[base + t];
            s_src[0][t] = m.y;
            s_dst[0][t] = m.z;
        }
        #pragma unroll
        for (int q = 0; q < 8; q++) {
            int row = q * 16 + rloc;
            int e = __shfl_sync(0xffffffffu, eidl, q + hh * 8);
            CP_ASYNC16(stageBase + (uint32_t)((row * 64 + chunk * 4) * 4),
                       edge_hid + (size_t)e * DD + chunk * 4);
        }
        CP_COMMIT();
    }

    #pragma unroll 1
    for (int it = 0; it < NT; it++) {
        int cb = it & 1, nb = cb ^ 1;

        // prefetch NEXT tile's meta into registers (off critical path)
        int eidl_n = 0;
        int4 m_n = make_int4(0, 0, 0, 0);
        if (it + 1 < NT) {
            int nbase = blk0 + (it + 1) * 128;
            eidl_n = g_meta[nbase + (l & 7) * 16 + 2 * w + ((l >> 3) & 1)].x;
            if (t < 128) m_n = g_meta[nbase + t];
        }

        CP_WAIT0();
        __syncthreads();                 // stage(tile it) visible; Hs free

        // convert stage f32 -> Ah f16 (smem-local, warp reads 512B contiguous)
        #pragma unroll
        for (int q = 0; q < 8; q++) {
            int row = q * 16 + rloc;
            float4 v = *(const float4*)(Sg + row * 64 + chunk * 4);
            __half2 h01 = __floats2half2_rn(v.x, v.y);
            __half2 h23 = __floats2half2_rn(v.z, v.w);
            uint2 pk = make_uint2(*(unsigned*)&h01, *(unsigned*)&h23);
            *(uint2*)(Ah + row * ASTR + chunk * 4) = pk;
        }
        __syncthreads();                 // Ah visible; stage free for next tile

        // issue next tile's gather NOW (hidden under mma+epilogue+reduce)
        if (it + 1 < NT) {
            if (t < 128) {
                s_src[nb][t] = m_n.y;
                s_dst[nb][t] = m_n.z;
            }
            #pragma unroll
            for (int q = 0; q < 8; q++) {
                int row = q * 16 + rloc;
                int e = __shfl_sync(0xffffffffu, eidl_n, q + hh * 8);
                CP_ASYNC16(stageBase + (uint32_t)((row * 64 + chunk * 4) * 4),
                           edge_hid + (size_t)e * DD + chunk * 4);
            }
            CP_COMMIT();
        }

        // ---- mma ----
        float C[2][8][4];
        #pragma unroll
        for (int mt = 0; mt < 2; mt++)
            #pragma unroll
            for (int nf = 0; nf < 8; nf++)
                { C[mt][nf][0] = C[mt][nf][1] = C[mt][nf][2] = C[mt][nf][3] = 0.f; }

        #pragma unroll
        for (int kt = 0; kt < 4; kt++) {
            unsigned a0, a1, a2, a3, a4, a5, a6, a7;
            LDM4(a0, a1, a2, a3, aA0 + kt * 32);
            LDM4(a4, a5, a6, a7, aA1 + kt * 32);
            #pragma unroll
            for (int pp = 0; pp < 4; pp++) {
                unsigned b0, b1, b2, b3;
                LDM4(b0, b1, b2, b3, aB + (uint32_t)(16 * pp * ASTR * 2) + kt * 32);
                mma_f16(C[0][2 * pp],     a0, a1, a2, a3, b0, b1);
                mma_f16(C[0][2 * pp + 1], a0, a1, a2, a3, b2, b3);
                mma_f16(C[1][2 * pp],     a4, a5, a6, a7, b0, b1);
                mma_f16(C[1][2 * pp + 1], a4, a5, a6, a7, b2, b3);
            }
        }

        // ---- epilogue: raw C -> f16 Hs ----
        {
            int r0 = 32 * wr + g;
            #pragma unroll
            for (int mt = 0; mt < 2; mt++) {
                #pragma unroll
                for (int nf = 0; nf < 8; nf++) {
                    int c0 = 64 * wcg + 8 * nf + q4 * 2;
                    __half2 v0 = __floats2half2_rn(C[mt][nf][0], C[mt][nf][1]);
                    __half2 v1 = __floats2half2_rn(C[mt][nf][2], C[mt][nf][3]);
                    int rA = r0 + mt * 16;
                    Hs2[rA * (HSTRH / 2) + (c0 >> 1)] = v0;
                    Hs2[(rA + 8) * (HSTRH / 2) + (c0 >> 1)] = v1;
                }
            }
        }
        __syncthreads();                 // Hs visible

        // ---- segmented reduce (fused ueproj add + relu), 8 strips of 16 rows ----
        {
            int c4 = t & 31, qr = t >> 5;
            int r0 = qr * 16;
            float acc0 = 0.f, acc1 = 0.f, acc2 = 0.f, acc3 = 0.f;
            int prev = s_dst[cb][r0];
            float* aggp = g_agg + (size_t)prev * HH + c4 * 4;
            #pragma unroll
            for (int gg = 0; gg < 2; gg++) {
                uint2 upk[8];
                #pragma unroll
                for (int i = 0; i < 8; i++)
                    upk[i] = *(const uint2*)(g_ueproj
                              + (size_t)s_src[cb][r0 + gg * 8 + i] * HH + c4 * 4);
                #pragma unroll
                for (int i = 0; i < 8; i++) {
                    int r = r0 + gg * 8 + i;
                    int d = s_dst[cb][r];
                    if (d != prev) {
                        atomicAdd(aggp + 0, acc0);
                        atomicAdd(aggp + 1, acc1);
                        atomicAdd(aggp + 2, acc2);
                        atomicAdd(aggp + 3, acc3);
                        acc0 = acc1 = acc2 = acc3 = 0.f;
                        prev = d;
                        aggp = g_agg + (size_t)prev * HH + c4 * 4;
                    }
                    uint2 pk = *(const uint2*)(Hs2 + r * (HSTRH / 2) + c4 * 2);
                    float2 hv0 = __half22float2(*(__half2*)&pk.x);
                    float2 hv1 = __half22float2(*(__half2*)&pk.y);
                    float2 u0 = __half22float2(*(__half2*)&upk[i].x);
                    float2 u1 = __half22float2(*(__half2*)&upk[i].y);
                    acc0 += fmaxf(hv0.x + u0.x, 0.f);
                    acc1 += fmaxf(hv0.y + u0.y, 0.f);
                    acc2 += fmaxf(hv1.x + u1.x, 0.f);
                    acc3 += fmaxf(hv1.y + u1.y, 0.f);
                }
            }
            atomicAdd(aggp + 0, acc0);
            atomicAdd(aggp + 1, acc1);
            atomicAdd(aggp + 2, acc2);
            atomicAdd(aggp + 3, acc3);
        }
    }
}

// ---------------- launch 4: final AP MLP + scratch cleanup ------------------
__global__ void __launch_bounds__(128) k_final(
    const float* __restrict__ ap_hid,
    const float* __restrict__ W1b, const float* __restrict__ b1b,
    const float* __restrict__ W2a, const float* __restrict__ b2a,
    const float* __restrict__ W2b, const float* __restrict__ b2b,
    float* __restrict__ out)
{
    __shared__ float Ss[16][128];
    __shared__ float Zs[16][192];
    __shared__ float Ys[16][128];
    __shared__ float sdeg[16];

    int t = threadIdx.x;
    int a0 = blockIdx.x * 16;

    for (int i = t; i < 16 * 128; i += 128)
        Ss[i >> 7][i & 127] = g_agg[(size_t)a0 * HH + i];
    if (t < 16) sdeg[t] = (float)g_cnt[a0 + t];
    for (int i = t; i < 16 * 64; i += 128)
        Zs[i >> 6][i & 63] = ap_hid[(size_t)a0 * DD + i];
    __syncthreads();

    // restore scratch invariant for the next kernel_launch call
    for (int i = t; i < 16 * 128; i += 128)
        g_agg[(size_t)a0 * HH + i] = 0.f;
    if (t < 16) g_cnt[a0 + t] = 0;

    // stage 1: Zs[r][64+c] = deg[r]*b1b[c] + sum_k Ss[r][k]*W1b[k][c]
    {
        int c = t;
        float acc[16];
        float bb = b1b[c];
        #pragma unroll
        for (int r = 0; r < 16; r++) acc[r] = sdeg[r] * bb;
        for (int k = 0; k < 128; k++) {
            float wv = W1b[k * HH + c];
            #pragma unroll
            for (int r = 0; r < 16; r++) acc[r] += Ss[r][k] * wv;
        }
        #pragma unroll
        for (int r = 0; r < 16; r++) Zs[r][64 + c] = acc[r];
    }
    __syncthreads();

    // stage 2: Ys = relu(Zs @ W2a + b2a)
    {
        int c = t;
        float acc[16];
        float bb = b2a[c];
        #pragma unroll
        for (int r = 0; r < 16; r++) acc[r] = bb;
        for (int k = 0; k < 192; k++) {
            float wv = W2a[k * HH + c];
            #pragma unroll
            for (int r = 0; r < 16; r++) acc[r] += Zs[r][k] * wv;
        }
        #pragma unroll
        for (int r = 0; r < 16; r++) Ys[r][c] = fmaxf(acc[r], 0.f);
    }
    __syncthreads();

    // stage 3: out = Ys @ W2b + b2b
    {
        int c = t & 63, rg = t >> 6;
        float acc[8];
        float bb = b2b[c];
        #pragma unroll
        for (int j = 0; j < 8; j++) acc[j] = bb;
        for (int k = 0; k < 128; k++) {
            float wv = W2b[k * DD + c];
            #pragma unroll
            for (int j = 0; j < 8; j++) acc[j] += Ys[rg * 8 + j][k] * wv;
        }
        #pragma unroll
        for (int j = 0; j < 8; j++)
            out[(size_t)(a0 + rg * 8 + j) * DD + c] = acc[j];
    }
}

// ---------------- launch ----------------------------------------------------
extern "C" void kernel_launch(void* const* d_in, const int* in_sizes, int n_in,
                              void* d_out, int out_size) {
    const float* ue_hid   = (const float*)d_in[0];
    const float* ap_hid   = (const float*)d_in[1];
    const float* edge_hid = (const float*)d_in[2];
    const int*   src      = (const int*)d_in[3];
    const int*   dst      = (const int*)d_in[4];
    const float* W1a      = (const float*)d_in[5];
    const float* b1a      = (const float*)d_in[6];
    const float* W1b      = (const float*)d_in[7];
    const float* b1b      = (const float*)d_in[8];
    const float* W2a      = (const float*)d_in[9];
    const float* b2a      = (const float*)d_in[10];
    const float* W2b      = (const float*)d_in[11];
    const float* b2b      = (const float*)d_in[12];
    float* out = (float*)d_out;

    cudaFuncSetAttribute(k_main, cudaFuncAttributeMaxDynamicSharedMemorySize, SMEM_MAIN);

    k_hist<<<SCAT_BLOCKS, 256>>>(dst);                                     // 0
    k_scan_prep<<<5, 1024>>>(W1a);                                         // 1
    k_scatter_ueproj<<<SCAT_BLOCKS + UEP_BLOCKS, 256>>>(src, dst,
                                                        ue_hid, W1a, b1a); // 2
    k_main<<<MAIN_BLOCKS, 256, SMEM_MAIN>>>(edge_hid);                     // 3 (profiled)
    k_final<<<N_AP / 16, 128>>>(ap_hid, W1b, b1b, W2a, b2a, W2b, b2b, out);// 4
}